// round 2
// baseline (speedup 1.0000x reference)
#include <cuda_runtime.h>
#include <math.h>

#define DD 256
#define HH 512
#define BB 128

// Pre-permuted, pre-masked weights in degree-sorted hidden order. net 0 = mu, 1 = lv.
__device__ float g_W0sT[2][DD * HH];   // [net][j][p]   layer-0 row for rank-1 y update
__device__ float g_W1c[2][HH * HH];    // [net][p][g]   layer-1 COLUMN-major (scatter)
__device__ float g_WoC[2][HH * DD];    // [net][g][j]   output COLUMN-major (scatter)
__device__ float g_WoDiag[2][HH];      // Wo[deg(g)][g] (the same-step "terms" weight)
__device__ float g_b0s[2][HH];
__device__ float g_b1s[2][HH];

// sorted position -> original hidden unit. degrees d(h) = (h % 255) + 1.
__device__ __forceinline__ int permf(int p) {
    if (p < 3) return (p == 0) ? 0 : ((p == 1) ? 255 : 510);
    if (p < 6) { int q = p - 3; return (q == 0) ? 1 : ((q == 1) ? 256 : 511); }
    int d = 3 + ((p - 6) >> 1);
    return (((p - 6) & 1) == 0) ? (d - 1) : (d + 254);
}
__device__ __forceinline__ int degf(int p) {
    if (p < 3) return 1;
    if (p < 6) return 2;
    return 3 + ((p - 6) >> 1);
}
// P(i) = #units with degree <= i (clamped)
__device__ __forceinline__ int Pfun(int i) {
    if (i <= 0) return 0;
    if (i == 1) return 3;
    int v = 2 * i + 2;
    return v > HH ? HH : v;
}
__device__ __forceinline__ float elus(float a) {
    return a > 0.f ? a : (__expf(a) - 1.f);
}

__global__ void setup_kernel(
    const float* __restrict__ W0m, const float* __restrict__ W1m, const float* __restrict__ Wom,
    const float* __restrict__ b0m, const float* __restrict__ b1m,
    const float* __restrict__ W0l, const float* __restrict__ W1l, const float* __restrict__ Wol,
    const float* __restrict__ b0l, const float* __restrict__ b1l)
{
    int tid = blockIdx.x * blockDim.x + threadIdx.x;
    int stride = gridDim.x * blockDim.x;

    for (int idx = tid; idx < HH * HH; idx += stride) {
        int p = idx >> 9, g = idx & 511;           // [p][g] column-major for scatter
        int pg = permf(g), pp = permf(p);
        float m = (degf(g) >= degf(p)) ? 1.f : 0.f;
        g_W1c[0][idx] = m * W1m[pg * HH + pp];
        g_W1c[1][idx] = m * W1l[pg * HH + pp];
    }
    for (int idx = tid; idx < DD * HH; idx += stride) {
        int j = idx >> 9, p = idx & 511;
        int pp = permf(p);
        int dp = degf(p);
        float m0 = (dp >= j + 1) ? 1.f : 0.f;
        g_W0sT[0][idx] = m0 * W0m[pp * DD + j];
        g_W0sT[1][idx] = m0 * W0l[pp * DD + j];
    }
    for (int idx = tid; idx < HH * DD; idx += stride) {
        int g = idx >> 8, j = idx & 255;           // [g][j] column-major for scatter
        int pg = permf(g);
        int dg = degf(g);
        float mo = (j >= dg) ? 1.f : 0.f;
        g_WoC[0][idx] = mo * Wom[j * HH + pg];
        g_WoC[1][idx] = mo * Wol[j * HH + pg];
    }
    for (int p = tid; p < HH; p += stride) {
        int pp = permf(p);
        int dp = degf(p);                          // 1..255, valid output row
        g_WoDiag[0][p] = Wom[dp * HH + pp];
        g_WoDiag[1][p] = Wol[dp * HH + pp];
        g_b0s[0][p] = b0m[pp]; g_b0s[1][p] = b0l[pp];
        g_b1s[0][p] = b1m[pp]; g_b1s[1][p] = b1l[pp];
    }
}

// One CTA per 4 batch elements (float4 over batch). 1024 threads:
// thread owns (net = tid>>9, idx = tid&511): its a0/a1 accumulators live in registers.
// tid<512 additionally owns output accumulator column (onet = tid>>8, j = tid&255).
__global__ __launch_bounds__(1024, 1) void made_kernel(
    const float* __restrict__ x,
    const float* __restrict__ bo_mu,
    const float* __restrict__ bo_lv,
    float* __restrict__ out)
{
    __shared__ float4 aout_sm[2][DD];     // [net][j] over 4 batches
    __shared__ float4 xs4[DD];            // x transposed over batch
    __shared__ float  bos_sm[2][DD];
    __shared__ float4 terms_sm[2][3];     // new-h1 diag contributions
    __shared__ float4 newh0_sm[2][3];     // h0 frozen last step
    __shared__ float4 newh1_sm[2][2][3];  // double-buffered new h1 values
    __shared__ float  ncols_sm[4][DD];

    const int tid = threadIdx.x;
    const int net = tid >> 9;
    const int idx = tid & 511;
    const int b4 = blockIdx.x << 2;

    // ---- init ----
    if (tid < 512) {
        aout_sm[tid >> 8][tid & 255] = make_float4(0.f, 0.f, 0.f, 0.f);
        bos_sm[tid >> 8][tid & 255] = (tid < 256) ? bo_mu[tid] : bo_lv[tid & 255];
    }
    {
        int ii = tid & 255, lb = tid >> 8;
        ((float*)xs4)[ii * 4 + lb] = x[(b4 + lb) * DD + ii];
    }
    if (tid < 6) {
        terms_sm[tid / 3][tid % 3] = make_float4(0.f, 0.f, 0.f, 0.f);
        newh0_sm[tid / 3][tid % 3] = make_float4(0.f, 0.f, 0.f, 0.f);
    }
    if (tid < 12) ((float4*)newh1_sm)[tid] = make_float4(0.f, 0.f, 0.f, 0.f);

    const float b0r = g_b0s[net][idx];
    const float b1r = g_b1s[net][idx];
    const float wod = g_WoDiag[net][idx];
    const float* __restrict__ W1base = g_W1c[net];
    const float* __restrict__ W0base = g_W0sT[net];
    const int onet = (tid >> 8) & 1;
    const int oj = tid & 255;
    const float* __restrict__ WoBase = g_WoC[onet];

    float4 a0 = make_float4(0.f, 0.f, 0.f, 0.f);
    float4 a1 = make_float4(0.f, 0.f, 0.f, 0.f);
    float w1c0 = 0.f, w1c1 = 0.f, w1c2 = 0.f;
    float woc0 = 0.f, woc1 = 0.f, woc2 = 0.f;
    float w0c = W0base[idx];
    float lvsum = 0.f;
    int Pim1 = 0;
    int ncC = 0, ncN = 3;

#pragma unroll 1
    for (int i = 0; i < DD; i++) {
        __syncthreads();  // A_i: publishes newh0 (prev Q), newh1 (prev P)

        // ---- P segment ----
        // a1 scatter: add last step's frozen h0 (zero-padded weights -> branch-free)
        {
            float4 h0;
            h0 = newh0_sm[net][0];
            a1.x = fmaf(h0.x, w1c0, a1.x); a1.y = fmaf(h0.y, w1c0, a1.y);
            a1.z = fmaf(h0.z, w1c0, a1.z); a1.w = fmaf(h0.w, w1c0, a1.w);
            h0 = newh0_sm[net][1];
            a1.x = fmaf(h0.x, w1c1, a1.x); a1.y = fmaf(h0.y, w1c1, a1.y);
            a1.z = fmaf(h0.z, w1c1, a1.z); a1.w = fmaf(h0.w, w1c1, a1.w);
            h0 = newh0_sm[net][2];
            a1.x = fmaf(h0.x, w1c2, a1.x); a1.y = fmaf(h0.y, w1c2, a1.y);
            a1.z = fmaf(h0.z, w1c2, a1.z); a1.w = fmaf(h0.w, w1c2, a1.w);
        }
        // aout scatter: add last step's frozen h1 into output accumulators
        if (tid < 512) {
            float4 ao = aout_sm[onet][oj];
            float4 h1;
            h1 = newh1_sm[(i + 1) & 1][onet][0];
            ao.x = fmaf(h1.x, woc0, ao.x); ao.y = fmaf(h1.y, woc0, ao.y);
            ao.z = fmaf(h1.z, woc0, ao.z); ao.w = fmaf(h1.w, woc0, ao.w);
            h1 = newh1_sm[(i + 1) & 1][onet][1];
            ao.x = fmaf(h1.x, woc1, ao.x); ao.y = fmaf(h1.y, woc1, ao.y);
            ao.z = fmaf(h1.z, woc1, ao.z); ao.w = fmaf(h1.w, woc1, ao.w);
            h1 = newh1_sm[(i + 1) & 1][onet][2];
            ao.x = fmaf(h1.x, woc2, ao.x); ao.y = fmaf(h1.y, woc2, ao.y);
            ao.z = fmaf(h1.z, woc2, ao.z); ao.w = fmaf(h1.w, woc2, ao.w);
            aout_sm[onet][oj] = ao;
        }
        // new h1 units (deg == i): owner thread computes elu + diag term
        {
            int slot = idx - Pim1;
            if ((unsigned)slot < (unsigned)ncC) {
                float4 h;
                h.x = elus(a1.x + b1r); h.y = elus(a1.y + b1r);
                h.z = elus(a1.z + b1r); h.w = elus(a1.w + b1r);
                newh1_sm[i & 1][net][slot] = h;
                terms_sm[net][slot] = make_float4(h.x * wod, h.y * wod, h.z * wod, h.w * wod);
            }
        }
        // prefetch weights for NEXT step's scatters (addresses data-independent)
        const int Pi = Pim1 + ncC;
        float w1n0 = (0 < ncN) ? W1base[(Pi + 0) * HH + idx] : 0.f;
        float w1n1 = (1 < ncN) ? W1base[(Pi + 1) * HH + idx] : 0.f;
        float w1n2 = (2 < ncN) ? W1base[(Pi + 2) * HH + idx] : 0.f;
        float won0 = 0.f, won1 = 0.f, won2 = 0.f;
        if (tid < 512) {
            won0 = (0 < ncC) ? WoBase[(Pim1 + 0) * DD + oj] : 0.f;
            won1 = (1 < ncC) ? WoBase[(Pim1 + 1) * DD + oj] : 0.f;
            won2 = (2 < ncC) ? WoBase[(Pim1 + 2) * DD + oj] : 0.f;
        }

        __syncthreads();  // B_i: publishes terms, aout updates

        // ---- Q segment: redundant combine on all threads ----
        float4 mu4 = aout_sm[0][i];
        float4 lv4 = aout_sm[1][i];
        {
            float4 t;
            t = terms_sm[0][0]; mu4.x += t.x; mu4.y += t.y; mu4.z += t.z; mu4.w += t.w;
            t = terms_sm[0][1]; mu4.x += t.x; mu4.y += t.y; mu4.z += t.z; mu4.w += t.w;
            t = terms_sm[1][0]; lv4.x += t.x; lv4.y += t.y; lv4.z += t.z; lv4.w += t.w;
            t = terms_sm[1][1]; lv4.x += t.x; lv4.y += t.y; lv4.z += t.z; lv4.w += t.w;
            if (ncC > 2) {
                t = terms_sm[0][2]; mu4.x += t.x; mu4.y += t.y; mu4.z += t.z; mu4.w += t.w;
                t = terms_sm[1][2]; lv4.x += t.x; lv4.y += t.y; lv4.z += t.z; lv4.w += t.w;
            }
        }
        const float bo0 = bos_sm[0][i], bo1 = bos_sm[1][i];
        mu4.x += bo0; mu4.y += bo0; mu4.z += bo0; mu4.w += bo0;
        lv4.x += bo1; lv4.y += bo1; lv4.z += bo1; lv4.w += bo1;
        const float4 x4 = xs4[i];
        const float ls0 = 0.5f * lv4.x, ls1 = 0.5f * lv4.y;
        const float ls2 = 0.5f * lv4.z, ls3 = 0.5f * lv4.w;
        const float n0 = __fdividef(x4.x - mu4.x, __expf(ls0) + 1e-12f);
        const float n1 = __fdividef(x4.y - mu4.y, __expf(ls1) + 1e-12f);
        const float n2 = __fdividef(x4.z - mu4.z, __expf(ls2) + 1e-12f);
        const float n3 = __fdividef(x4.w - mu4.w, __expf(ls3) + 1e-12f);
        if (tid < 4)
            lvsum += (tid == 0) ? ls0 : (tid == 1) ? ls1 : (tid == 2) ? ls2 : ls3;
        if (tid == 0) {
            ncols_sm[0][i] = n0; ncols_sm[1][i] = n1;
            ncols_sm[2][i] = n2; ncols_sm[3][i] = n3;
        }
        // rank-1 layer-0 update (own unit, own net; masked weights)
        a0.x = fmaf(n0, w0c, a0.x); a0.y = fmaf(n1, w0c, a0.y);
        a0.z = fmaf(n2, w0c, a0.z); a0.w = fmaf(n3, w0c, a0.w);
        // freeze new h0 units (deg == i+1)
        {
            int fs = idx - Pi;
            if ((unsigned)fs < (unsigned)ncN) {
                float4 h;
                h.x = elus(a0.x + b0r); h.y = elus(a0.y + b0r);
                h.z = elus(a0.z + b0r); h.w = elus(a0.w + b0r);
                newh0_sm[net][fs] = h;
            }
        }
        // prefetch next w0 row
        const float w0nl = (i + 1 < DD) ? W0base[(i + 1) * HH + idx] : 0.f;

        // rotate step state
        w0c = w0nl;
        w1c0 = w1n0; w1c1 = w1n1; w1c2 = w1n2;
        woc0 = won0; woc1 = won1; woc2 = won2;
        Pim1 = Pi;
        ncC = ncN;
        ncN = Pfun(i + 2) - Pfun(i + 1);
    }

    __syncthreads();
    {
        int lb = tid >> 8, ii = tid & 255;
        out[(b4 + lb) * DD + ii] = ncols_sm[lb][ii];
    }
    if (tid < 4) out[BB * DD + b4 + tid] = lvsum;
}

extern "C" void kernel_launch(void* const* d_in, const int* in_sizes, int n_in,
                              void* d_out, int out_size) {
    const float* xx   = (const float*)d_in[0];
    const float* muW0 = (const float*)d_in[1];
    const float* mub0 = (const float*)d_in[2];
    const float* muW1 = (const float*)d_in[3];
    const float* mub1 = (const float*)d_in[4];
    const float* muWo = (const float*)d_in[5];
    const float* mubo = (const float*)d_in[6];
    const float* lvW0 = (const float*)d_in[7];
    const float* lvb0 = (const float*)d_in[8];
    const float* lvW1 = (const float*)d_in[9];
    const float* lvb1 = (const float*)d_in[10];
    const float* lvWo = (const float*)d_in[11];
    const float* lvbo = (const float*)d_in[12];
    float* out = (float*)d_out;

    setup_kernel<<<512, 256>>>(muW0, muW1, muWo, mub0, mub1,
                               lvW0, lvW1, lvWo, lvb0, lvb1);
    made_kernel<<<BB / 4, 1024>>>(xx, mubo, lvbo, out);
}

// round 3
// speedup vs baseline: 1.6049x; 1.6049x over previous
#include <cuda_runtime.h>
#include <math.h>

#define DD 256
#define HH 512
#define BB 128

// Pre-permuted, pre-masked weights in degree-sorted hidden order. net 0 = mu, 1 = lv.
__device__ float g_W0sT[2][DD * HH];   // [net][j][p]   layer-0 row (rank-1 y update)
__device__ float g_W1c[2][HH * HH];    // [net][p][g]   layer-1 column-major (scatter)
__device__ float g_WoC[2][HH * DD];    // [net][g][j]   output column-major (scatter)
__device__ float g_WoDiag[2][HH];      // Wo[deg(g)][g] same-step diag weight
__device__ float g_b0s[2][HH];
__device__ float g_b1s[2][HH];

__device__ __forceinline__ int permf(int p) {
    if (p < 3) return (p == 0) ? 0 : ((p == 1) ? 255 : 510);
    if (p < 6) { int q = p - 3; return (q == 0) ? 1 : ((q == 1) ? 256 : 511); }
    int d = 3 + ((p - 6) >> 1);
    return (((p - 6) & 1) == 0) ? (d - 1) : (d + 254);
}
__device__ __forceinline__ int degf(int p) {
    if (p < 3) return 1;
    if (p < 6) return 2;
    return 3 + ((p - 6) >> 1);
}
__device__ __forceinline__ float elus(float a) {
    return a > 0.f ? a : (__expf(a) - 1.f);
}

__global__ void setup_kernel(
    const float* __restrict__ W0m, const float* __restrict__ W1m, const float* __restrict__ Wom,
    const float* __restrict__ b0m, const float* __restrict__ b1m,
    const float* __restrict__ W0l, const float* __restrict__ W1l, const float* __restrict__ Wol,
    const float* __restrict__ b0l, const float* __restrict__ b1l)
{
    int tid = blockIdx.x * blockDim.x + threadIdx.x;
    int stride = gridDim.x * blockDim.x;

    for (int idx = tid; idx < HH * HH; idx += stride) {
        int p = idx >> 9, g = idx & 511;
        int pg = permf(g), pp = permf(p);
        float m = (degf(g) >= degf(p)) ? 1.f : 0.f;
        g_W1c[0][idx] = m * W1m[pg * HH + pp];
        g_W1c[1][idx] = m * W1l[pg * HH + pp];
    }
    for (int idx = tid; idx < DD * HH; idx += stride) {
        int j = idx >> 9, p = idx & 511;
        int pp = permf(p);
        int dp = degf(p);
        float m0 = (dp >= j + 1) ? 1.f : 0.f;
        g_W0sT[0][idx] = m0 * W0m[pp * DD + j];
        g_W0sT[1][idx] = m0 * W0l[pp * DD + j];
    }
    for (int idx = tid; idx < HH * DD; idx += stride) {
        int g = idx >> 8, j = idx & 255;
        int pg = permf(g);
        int dg = degf(g);
        float mo = (j >= dg) ? 1.f : 0.f;
        g_WoC[0][idx] = mo * Wom[j * HH + pg];
        g_WoC[1][idx] = mo * Wol[j * HH + pg];
    }
    for (int p = tid; p < HH; p += stride) {
        int pp = permf(p);
        int dp = degf(p);
        g_WoDiag[0][p] = Wom[dp * HH + pp];
        g_WoDiag[1][p] = Wol[dp * HH + pp];
        g_b0s[0][p] = b0m[pp]; g_b0s[1][p] = b0l[pp];
        g_b1s[0][p] = b1m[pp]; g_b1s[1][p] = b1l[pp];
    }
}

// One CTA per 2 batch elements. 512 threads; thread tid owns hidden unit tid for
// BOTH nets (a0/a1 float2 accumulators over the 2 batch lanes live in registers),
// plus output-column accumulator (onet = tid>>8, oj = tid&255) in registers.
__global__ __launch_bounds__(512, 1) void made_kernel(
    const float* __restrict__ x,
    const float* __restrict__ bo_mu,
    const float* __restrict__ bo_lv,
    float* __restrict__ out)
{
    __shared__ float4 bosx[DD];        // (bo_mu, bo_lv, x_l0, x_l1)
    __shared__ float4 newh0[3];        // (n0l0, n0l1, n1l0, n1l1) per slot
    __shared__ float2 newh1[2][3][2];  // [buf][slot][net] over 2 lanes
    __shared__ float4 terms[3];        // (mu_l0, mu_l1, lv_l0, lv_l1)
    __shared__ float4 pub;             // aout col i: (mu0, mu1, lv0, lv1)

    const int tid = threadIdx.x;
    const int b2 = blockIdx.x << 1;
    const int onet = tid >> 8, oj = tid & 255;

    if (tid < DD)
        bosx[tid] = make_float4(bo_mu[tid], bo_lv[tid],
                                x[(b2 + 0) * DD + tid], x[(b2 + 1) * DD + tid]);
    if (tid < 3) {
        newh0[tid] = make_float4(0.f, 0.f, 0.f, 0.f);
        terms[tid] = make_float4(0.f, 0.f, 0.f, 0.f);
    }
    if (tid >= 16 && tid < 28)
        ((float2*)newh1)[tid - 16] = make_float2(0.f, 0.f);
    if (tid == 28) pub = make_float4(0.f, 0.f, 0.f, 0.f);

    const float b0r0 = g_b0s[0][tid], b0r1 = g_b0s[1][tid];
    const float b1r0 = g_b1s[0][tid], b1r1 = g_b1s[1][tid];
    const float wod0 = g_WoDiag[0][tid], wod1 = g_WoDiag[1][tid];

    const float* __restrict__ W1p0 = g_W1c[0] + tid;
    const float* __restrict__ W1p1 = g_W1c[1] + tid;
    const float* __restrict__ Wop  = g_WoC[onet] + oj;
    const float* __restrict__ W0p0 = g_W0sT[0] + tid;
    const float* __restrict__ W0p1 = g_W0sT[1] + tid;

    float2 a1n0 = {0.f, 0.f}, a1n1 = {0.f, 0.f};
    float2 a0n0 = {0.f, 0.f}, a0n1 = {0.f, 0.f};
    float2 aout = {0.f, 0.f};
    float w1s0n0 = 0.f, w1s0n1 = 0.f, w1s1n0 = 0.f, w1s1n1 = 0.f;
    float w1s2n0 = 0.f, w1s2n1 = 0.f;
    float wos0 = 0.f, wos1 = 0.f, wos2 = 0.f;
    float w0c0 = W0p0[0], w0c1 = W0p1[0];
    float lvs0 = 0.f, lvs1 = 0.f;

    int Pim1 = 0, Pi = 0;
    int cp = 0;  // nc(i-1): h1 slots for aout scatter
    int cc = 0;  // nc(i):   h0 slots, h1 owners, terms
    int cn = 3;  // nc(i+1): freeze slots

#pragma unroll 1
    for (int i = 0; i < DD; i++) {
        __syncthreads();  // A: newh0 (Q_{i-1}), newh1 (P_{i-1}) visible

        // ---- P: a1 scatter of new h0 (deg i) ----
        {
            float4 h0a = newh0[0], h0b = newh0[1];
            a1n0.x = fmaf(h0a.x, w1s0n0, a1n0.x);
            a1n0.y = fmaf(h0a.y, w1s0n0, a1n0.y);
            a1n1.x = fmaf(h0a.z, w1s0n1, a1n1.x);
            a1n1.y = fmaf(h0a.w, w1s0n1, a1n1.y);
            a1n0.x = fmaf(h0b.x, w1s1n0, a1n0.x);
            a1n0.y = fmaf(h0b.y, w1s1n0, a1n0.y);
            a1n1.x = fmaf(h0b.z, w1s1n1, a1n1.x);
            a1n1.y = fmaf(h0b.w, w1s1n1, a1n1.y);
            if (cc > 2) {
                float4 h0c = newh0[2];
                a1n0.x = fmaf(h0c.x, w1s2n0, a1n0.x);
                a1n0.y = fmaf(h0c.y, w1s2n0, a1n0.y);
                a1n1.x = fmaf(h0c.z, w1s2n1, a1n1.x);
                a1n1.y = fmaf(h0c.w, w1s2n1, a1n1.y);
            }
        }
        // ---- P: aout scatter of h1 frozen last step (deg i-1) ----
        {
            const int rb = (i + 1) & 1;
            float2 h1a = newh1[rb][0][onet];
            float2 h1b = newh1[rb][1][onet];
            aout.x = fmaf(h1a.x, wos0, aout.x);
            aout.y = fmaf(h1a.y, wos0, aout.y);
            aout.x = fmaf(h1b.x, wos1, aout.x);
            aout.y = fmaf(h1b.y, wos1, aout.y);
            if (cp > 2) {
                float2 h1c = newh1[rb][2][onet];
                aout.x = fmaf(h1c.x, wos2, aout.x);
                aout.y = fmaf(h1c.y, wos2, aout.y);
            }
        }
        // publish output column i
        if (oj == i) {
            if (onet == 0) { pub.x = aout.x; pub.y = aout.y; }
            else           { pub.z = aout.x; pub.w = aout.y; }
        }
        // new h1 owners (deg i): idx in [Pim1, Pi)
        {
            unsigned sl = (unsigned)(tid - Pim1);
            if (sl < (unsigned)cc) {
                float h10 = elus(a1n0.x + b1r0);
                float h11 = elus(a1n0.y + b1r0);
                float h12 = elus(a1n1.x + b1r1);
                float h13 = elus(a1n1.y + b1r1);
                newh1[i & 1][sl][0] = make_float2(h10, h11);
                newh1[i & 1][sl][1] = make_float2(h12, h13);
                terms[sl] = make_float4(h10 * wod0, h11 * wod0, h12 * wod1, h13 * wod1);
            }
        }
        // prefetch next step's scatter weights (addresses data-independent)
        float nw1a0 = 0.f, nw1a1 = 0.f, nw1b0 = 0.f, nw1b1 = 0.f;
        float nw1c0 = 0.f, nw1c1 = 0.f;
        if (cn > 0) {
            nw1a0 = W1p0[(Pi + 0) << 9]; nw1a1 = W1p1[(Pi + 0) << 9];
            nw1b0 = W1p0[(Pi + 1) << 9]; nw1b1 = W1p1[(Pi + 1) << 9];
            if (cn > 2) { nw1c0 = W1p0[(Pi + 2) << 9]; nw1c1 = W1p1[(Pi + 2) << 9]; }
        }
        float nwo0 = 0.f, nwo1 = 0.f, nwo2 = 0.f;
        if (cc > 0) {
            nwo0 = Wop[(Pim1 + 0) << 8];
            nwo1 = Wop[(Pim1 + 1) << 8];
            if (cc > 2) nwo2 = Wop[(Pim1 + 2) << 8];
        }

        __syncthreads();  // B: pub, terms visible

        // ---- Q: redundant lean combine ----
        float4 pb = pub;
        float4 t0 = terms[0], t1 = terms[1];
        float mu0 = pb.x + t0.x + t1.x;
        float mu1 = pb.y + t0.y + t1.y;
        float lv0 = pb.z + t0.z + t1.z;
        float lv1 = pb.w + t0.w + t1.w;
        if (cc > 2) {
            float4 t2 = terms[2];
            mu0 += t2.x; mu1 += t2.y; lv0 += t2.z; lv1 += t2.w;
        }
        float4 bx = bosx[i];
        mu0 += bx.x; mu1 += bx.x;
        lv0 += bx.y; lv1 += bx.y;
        const float ls0 = 0.5f * lv0, ls1 = 0.5f * lv1;
        const float n0 = (bx.z - mu0) * __expf(-ls0);
        const float n1 = (bx.w - mu1) * __expf(-ls1);
        lvs0 += ls0; lvs1 += ls1;
        if (tid == 0) {
            out[(b2 + 0) * DD + i] = n0;
            out[(b2 + 1) * DD + i] = n1;
        }
        // rank-1 layer-0 update
        a0n0.x = fmaf(n0, w0c0, a0n0.x);
        a0n0.y = fmaf(n1, w0c0, a0n0.y);
        a0n1.x = fmaf(n0, w0c1, a0n1.x);
        a0n1.y = fmaf(n1, w0c1, a0n1.y);
        // freeze new h0 (deg i+1): idx in [Pi, Pi+cn)
        {
            unsigned fs = (unsigned)(tid - Pi);
            if (fs < (unsigned)cn) {
                newh0[fs] = make_float4(
                    elus(a0n0.x + b0r0), elus(a0n0.y + b0r0),
                    elus(a0n1.x + b0r1), elus(a0n1.y + b0r1));
            }
        }
        // prefetch next layer-0 row
        if (i + 1 < DD) {
            w0c0 = W0p0[(i + 1) << 9];
            w0c1 = W0p1[(i + 1) << 9];
        }
        // rotate step state
        w1s0n0 = nw1a0; w1s0n1 = nw1a1;
        w1s1n0 = nw1b0; w1s1n1 = nw1b1;
        w1s2n0 = nw1c0; w1s2n1 = nw1c1;
        wos0 = nwo0; wos1 = nwo1; wos2 = nwo2;
        Pim1 = Pi; Pi += cn;
        cp = cc; cc = cn;
        cn = (i == 0) ? 3 : ((i <= 253) ? 2 : 0);
    }

    if (tid == 0) {
        out[BB * DD + b2 + 0] = lvs0;
        out[BB * DD + b2 + 1] = lvs1;
    }
}

extern "C" void kernel_launch(void* const* d_in, const int* in_sizes, int n_in,
                              void* d_out, int out_size) {
    const float* xx   = (const float*)d_in[0];
    const float* muW0 = (const float*)d_in[1];
    const float* mub0 = (const float*)d_in[2];
    const float* muW1 = (const float*)d_in[3];
    const float* mub1 = (const float*)d_in[4];
    const float* muWo = (const float*)d_in[5];
    const float* mubo = (const float*)d_in[6];
    const float* lvW0 = (const float*)d_in[7];
    const float* lvb0 = (const float*)d_in[8];
    const float* lvW1 = (const float*)d_in[9];
    const float* lvb1 = (const float*)d_in[10];
    const float* lvWo = (const float*)d_in[11];
    const float* lvbo = (const float*)d_in[12];
    float* out = (float*)d_out;

    setup_kernel<<<512, 256>>>(muW0, muW1, muWo, mub0, mub1,
                               lvW0, lvW1, lvWo, lvb0, lvb1);
    made_kernel<<<BB / 2, 512>>>(xx, mubo, lvbo, out);
}

// round 4
// speedup vs baseline: 2.0692x; 1.2893x over previous
#include <cuda_runtime.h>
#include <cuda_fp16.h>
#include <math.h>

#define DD 256
#define HH 512
#define BB 128

// Wide scatter weights, fp16, pre-masked, degree-sorted. half2 packs (mu, lv).
__device__ __half2 g_W0h[DD * HH];    // [j][u]: ncol(j) -> a0[u]
__device__ __half2 g_W1h[HH * HH];    // [p][u]: h0[p] -> a1[u]
__device__ __half  g_Woh[2 * HH * DD];// [net][g][col]: h1[g] -> aout[col]
// Combiner urgent records (fp32)
__device__ float g_recS[256 * 40];    // steady 2-slot layout (used i>=4)
__device__ float g_recW[4 * 68];      // warm-up 3-slot layout (i<4)

__device__ __forceinline__ int permf(int p) {
    if (p < 3) return (p == 0) ? 0 : ((p == 1) ? 255 : 510);
    if (p < 6) { int q = p - 3; return (q == 0) ? 1 : ((q == 1) ? 256 : 511); }
    int d = 3 + ((p - 6) >> 1);
    return (((p - 6) & 1) == 0) ? (d - 1) : (d + 254);
}
__device__ __forceinline__ int degf(int p) {
    if (p < 3) return 1;
    if (p < 6) return 2;
    return 3 + ((p - 6) >> 1);
}
__device__ __forceinline__ int Pof(int k) {
    if (k <= 0) return 0;
    if (k == 1) return 3;
    int v = 2 * k + 2;
    return v > HH ? HH : v;
}
__device__ __forceinline__ float elu1(float a) {
    float e = __expf(a) - 1.f;
    return a > 0.f ? a : e;
}

__global__ void setup_kernel(
    const float* __restrict__ W0m, const float* __restrict__ W1m, const float* __restrict__ Wom,
    const float* __restrict__ b0m, const float* __restrict__ b1m,
    const float* __restrict__ W0l, const float* __restrict__ W1l, const float* __restrict__ Wol,
    const float* __restrict__ b0l, const float* __restrict__ b1l,
    const float* __restrict__ bom, const float* __restrict__ bol)
{
    int tid = blockIdx.x * blockDim.x + threadIdx.x;
    int stride = gridDim.x * blockDim.x;

    for (int idx = tid; idx < HH * HH; idx += stride) {
        int p = idx >> 9, u = idx & 511;
        float m = (degf(u) >= degf(p)) ? 1.f : 0.f;
        int ou = permf(u), op = permf(p);
        g_W1h[idx] = __floats2half2_rn(m * W1m[ou * HH + op], m * W1l[ou * HH + op]);
    }
    for (int idx = tid; idx < DD * HH; idx += stride) {
        int j = idx >> 9, u = idx & 511;
        float m = (degf(u) >= j + 1) ? 1.f : 0.f;
        int ou = permf(u);
        g_W0h[idx] = __floats2half2_rn(m * W0m[ou * DD + j], m * W0l[ou * DD + j]);
    }
    for (int idx = tid; idx < 2 * HH * DD; idx += stride) {
        int n = idx >> 17;
        int rem = idx & (HH * DD - 1);
        int g = rem >> 8, col = rem & 255;
        float m = (col >= degf(g)) ? 1.f : 0.f;
        const float* Wo = n ? Wol : Wom;
        g_Woh[idx] = __float2half_rn(m * Wo[col * HH + permf(g)]);
    }
    // ---- combiner records ----
    for (int i = tid; i < 256; i += stride) {
        int cB = Pof(i - 1), cc = Pof(i) - cB;
        int pB = Pof(i - 2), cp = Pof(i - 1) - pB;
        // steady layout (2 slots), valid for i>=4
        {
            float* r = g_recS + i * 40;
            for (int k = 0; k < 40; k++) r[k] = 0.f;
            int c2 = cc < 2 ? cc : 2, p2 = cp < 2 ? cp : 2;
            for (int s = 0; s < c2; s++) {
                int p = permf(cB + s);
                if (i >= 1) { r[0 + 2 * s] = W0m[p * DD + (i - 1)]; r[1 + 2 * s] = W0l[p * DD + (i - 1)]; }
                r[4 + 2 * s] = b0m[p];  r[5 + 2 * s] = b0l[p];
                r[8 + 2 * s] = b1m[p];  r[9 + 2 * s] = b1l[p];
                r[32 + 2 * s] = Wom[i * HH + p]; r[33 + 2 * s] = Wol[i * HH + p];
            }
            for (int sp = 0; sp < p2; sp++) {
                int pp = permf(pB + sp);
                r[28 + 2 * sp] = Wom[i * HH + pp]; r[29 + 2 * sp] = Wol[i * HH + pp];
                for (int sc = 0; sc < c2; sc++) {
                    int g = permf(cB + sc);
                    r[12 + sp * 4 + 2 * sc] = W1m[g * HH + pp];
                    r[13 + sp * 4 + 2 * sc] = W1l[g * HH + pp];
                }
            }
            for (int sp = 0; sp < c2; sp++)
                for (int sc = 0; sc < c2; sc++) {
                    int pp = permf(cB + sp), g = permf(cB + sc);
                    r[20 + sp * 4 + 2 * sc] = W1m[g * HH + pp];
                    r[21 + sp * 4 + 2 * sc] = W1l[g * HH + pp];
                }
            r[36] = bom[i]; r[37] = bol[i];
        }
        // warm-up layout (3 slots), i<4
        if (i < 4) {
            float* r = g_recW + i * 68;
            for (int k = 0; k < 68; k++) r[k] = 0.f;
            for (int s = 0; s < cc; s++) {
                int p = permf(cB + s);
                if (i >= 1) { r[0 + 2 * s] = W0m[p * DD + (i - 1)]; r[1 + 2 * s] = W0l[p * DD + (i - 1)]; }
                r[6 + 2 * s] = b0m[p];  r[7 + 2 * s] = b0l[p];
                r[12 + 2 * s] = b1m[p]; r[13 + 2 * s] = b1l[p];
                r[60 + 2 * s] = Wom[i * HH + p]; r[61 + 2 * s] = Wol[i * HH + p];
            }
            for (int sp = 0; sp < cp; sp++) {
                int pp = permf(pB + sp);
                r[54 + 2 * sp] = Wom[i * HH + pp]; r[55 + 2 * sp] = Wol[i * HH + pp];
                for (int sc = 0; sc < cc; sc++) {
                    int g = permf(cB + sc);
                    r[18 + sp * 6 + 2 * sc] = W1m[g * HH + pp];
                    r[19 + sp * 6 + 2 * sc] = W1l[g * HH + pp];
                }
            }
            for (int sp = 0; sp < cc; sp++)
                for (int sc = 0; sc < cc; sc++) {
                    int pp = permf(cB + sp), g = permf(cB + sc);
                    r[36 + sp * 6 + 2 * sc] = W1m[g * HH + pp];
                    r[37 + sp * 6 + 2 * sc] = W1l[g * HH + pp];
                }
            r[66] = bom[i]; r[67] = bol[i];
        }
    }
}

// smem layout (floats)
#define OFF_RECS 0
#define OFF_RECW 10240
#define OFF_XS   10512
#define OFF_PUB  10768
#define OFF_PAR  10800
#define SM_FLOATS 10832

struct CombState {
    float h0p[3][2], h1p[3][2];
    float ncol, lvsum;
};

// steady (2-slot) combiner step
__device__ __forceinline__ void comb_steady(const float* __restrict__ pr, const float* __restrict__ r,
                                            float xi, CombState& st, float* __restrict__ pu,
                                            float* __restrict__ outp)
{
    float h0c[2][2], h1c[2][2];
#pragma unroll
    for (int s = 0; s < 2; s++)
#pragma unroll
        for (int n = 0; n < 2; n++)
            h0c[s][n] = elu1(pr[2 * s + n] + st.ncol * r[2 * s + n] + r[4 + 2 * s + n]);
#pragma unroll
    for (int sc = 0; sc < 2; sc++)
#pragma unroll
        for (int n = 0; n < 2; n++) {
            float a = pr[6 + 2 * sc + n] + r[8 + 2 * sc + n];
#pragma unroll
            for (int sp = 0; sp < 2; sp++) a = fmaf(st.h0p[sp][n], r[12 + sp * 4 + 2 * sc + n], a);
#pragma unroll
            for (int sp = 0; sp < 2; sp++) a = fmaf(h0c[sp][n], r[20 + sp * 4 + 2 * sc + n], a);
            h1c[sc][n] = elu1(a);
        }
    float mu = pr[12] + r[36];
    float lv = pr[13] + r[37];
#pragma unroll
    for (int sp = 0; sp < 2; sp++) { mu = fmaf(st.h1p[sp][0], r[28 + 2 * sp], mu); lv = fmaf(st.h1p[sp][1], r[29 + 2 * sp], lv); }
#pragma unroll
    for (int sc = 0; sc < 2; sc++) { mu = fmaf(h1c[sc][0], r[32 + 2 * sc], mu); lv = fmaf(h1c[sc][1], r[33 + 2 * sc], lv); }
    float ls = 0.5f * lv;
    float nc = (xi - mu) * __expf(-ls);
    st.lvsum += ls; st.ncol = nc;
    *outp = nc;
    pu[0] = nc;
#pragma unroll
    for (int s = 0; s < 2; s++)
#pragma unroll
        for (int n = 0; n < 2; n++) {
            pu[1 + 2 * s + n] = h0c[s][n]; pu[7 + 2 * s + n] = h1c[s][n];
            st.h0p[s][n] = h0c[s][n]; st.h1p[s][n] = h1c[s][n];
        }
    pu[5] = 0.f; pu[6] = 0.f; pu[11] = 0.f; pu[12] = 0.f;
    st.h0p[2][0] = st.h0p[2][1] = st.h1p[2][0] = st.h1p[2][1] = 0.f;
}

// warm-up (3-slot) combiner step
__device__ __forceinline__ void comb_warm(const float* __restrict__ pr, const float* __restrict__ r,
                                          float xi, CombState& st, float* __restrict__ pu,
                                          float* __restrict__ outp)
{
    float h0c[3][2], h1c[3][2];
#pragma unroll
    for (int s = 0; s < 3; s++)
#pragma unroll
        for (int n = 0; n < 2; n++)
            h0c[s][n] = elu1(pr[2 * s + n] + st.ncol * r[2 * s + n] + r[6 + 2 * s + n]);
#pragma unroll
    for (int sc = 0; sc < 3; sc++)
#pragma unroll
        for (int n = 0; n < 2; n++) {
            float a = pr[6 + 2 * sc + n] + r[12 + 2 * sc + n];
            // NOTE: pa1 lives at pr[6..11]; reuse index below correctly:
            a = pr[6 + 2 * sc + n] + r[12 + 2 * sc + n];
#pragma unroll
            for (int sp = 0; sp < 3; sp++) a = fmaf(st.h0p[sp][n], r[18 + sp * 6 + 2 * sc + n], a);
#pragma unroll
            for (int sp = 0; sp < 3; sp++) a = fmaf(h0c[sp][n], r[36 + sp * 6 + 2 * sc + n], a);
            h1c[sc][n] = elu1(a);
        }
    float mu = pr[12] + r[66];
    float lv = pr[13] + r[67];
#pragma unroll
    for (int sp = 0; sp < 3; sp++) { mu = fmaf(st.h1p[sp][0], r[54 + 2 * sp], mu); lv = fmaf(st.h1p[sp][1], r[55 + 2 * sp], lv); }
#pragma unroll
    for (int sc = 0; sc < 3; sc++) { mu = fmaf(h1c[sc][0], r[60 + 2 * sc], mu); lv = fmaf(h1c[sc][1], r[61 + 2 * sc], lv); }
    float ls = 0.5f * lv;
    float nc = (xi - mu) * __expf(-ls);
    st.lvsum += ls; st.ncol = nc;
    *outp = nc;
    pu[0] = nc;
#pragma unroll
    for (int s = 0; s < 3; s++)
#pragma unroll
        for (int n = 0; n < 2; n++) {
            pu[1 + 2 * s + n] = h0c[s][n]; pu[7 + 2 * s + n] = h1c[s][n];
            st.h0p[s][n] = h0c[s][n]; st.h1p[s][n] = h1c[s][n];
        }
}

__device__ __forceinline__ void load_stage(int j, int u, int woBase,
                                           __half2& w0, __half2* w1, __half* wo)
{
    int w0row = j - 1;
    w0row = w0row < 0 ? 0 : (w0row > DD - 1 ? DD - 1 : w0row);
    w0 = g_W0h[w0row * HH + u];
    int pB = Pof(j - 2);
#pragma unroll
    for (int s = 0; s < 3; s++) {
        int row = pB + s;
        if (row > HH - 1) row = HH - 1;
        w1[s] = g_W1h[row * HH + u];
        wo[s] = g_Woh[woBase + row * DD];
    }
}

// 128 CTAs (one batch element each), 544 threads:
// tid<512: wide owner of unit tid (both nets) + output column (tid>>8 net, tid&255 col)
// tid==512: combiner (the serial critical path)
__global__ __launch_bounds__(544, 1) void made_kernel(
    const float* __restrict__ x, float* __restrict__ out)
{
    __shared__ float SM[SM_FLOATS];

    const int tid = threadIdx.x;
    const int b = blockIdx.x;

    // init: copy records, x; zero pub/par
    {
        const float4* src = (const float4*)g_recS;
        float4* dst = (float4*)(SM + OFF_RECS);
        for (int k = tid; k < (256 * 40) / 4; k += 544) dst[k] = src[k];
        for (int k = tid; k < 4 * 68; k += 544) SM[OFF_RECW + k] = g_recW[k];
        if (tid < 256) SM[OFF_XS + tid] = x[b * DD + tid];
        for (int k = tid; k < 64; k += 544) SM[OFF_PUB + k] = 0.f;
    }

    const int u = tid < 512 ? tid : 0;
    const int du = degf(u);
    const int su = u - Pof(du - 1);
    const int onet = (tid >> 8) & 1;
    const int ocol = tid & 255;
    const int woBase = onet * HH * DD + ocol;

    float a0n0 = 0.f, a0n1 = 0.f, a1n0 = 0.f, a1n1 = 0.f, aout = 0.f;

    __half2 w0A, w1A[3], w0B, w1B[3];
    __half woA[3], woB[3];
    load_stage(0, u, woBase, w0A, w1A, woA);
    load_stage(1, u, woBase, w0B, w1B, woB);

    CombState st;
#pragma unroll
    for (int s = 0; s < 3; s++)
#pragma unroll
        for (int n = 0; n < 2; n++) { st.h0p[s][n] = 0.f; st.h1p[s][n] = 0.f; }
    st.ncol = 0.f; st.lvsum = 0.f;

    __syncthreads();

#pragma unroll 1
    for (int i = 0; i < DD; i++) {
        if (tid < 512) {
            const float* pb = &SM[OFF_PUB + (((i + 1) & 1) << 4)];
            float ncp = pb[0];
            float2 w0f = __half22float2(w0A);
            a0n0 = fmaf(ncp, w0f.x, a0n0);
            a0n1 = fmaf(ncp, w0f.y, a0n1);
#pragma unroll
            for (int s = 0; s < 3; s++) {
                float2 wf = __half22float2(w1A[s]);
                a1n0 = fmaf(pb[1 + 2 * s], wf.x, a1n0);
                a1n1 = fmaf(pb[2 + 2 * s], wf.y, a1n1);
                aout = fmaf(pb[7 + 2 * s + onet], __half2float(woA[s]), aout);
            }
            float* pw = &SM[OFF_PAR + (((i + 1) & 1) << 4)];
            if (du == i + 1) {
                pw[2 * su] = a0n0; pw[2 * su + 1] = a0n1;
                pw[6 + 2 * su] = a1n0; pw[7 + 2 * su] = a1n1;
            }
            if (ocol == i + 1) pw[12 + onet] = aout;
            // rotate stages, prefetch i+2
            w0A = w0B;
#pragma unroll
            for (int s = 0; s < 3; s++) { w1A[s] = w1B[s]; woA[s] = woB[s]; }
            load_stage(i + 2, u, woBase, w0B, w1B, woB);
        } else if (tid == 512) {
            const float* pr = &SM[OFF_PAR + ((i & 1) << 4)];
            float* pu = &SM[OFF_PUB + ((i & 1) << 4)];
            float xi = SM[OFF_XS + i];
            if (i >= 4)
                comb_steady(pr, SM + OFF_RECS + i * 40, xi, st, pu, &out[b * DD + i]);
            else
                comb_warm(pr, SM + OFF_RECW + i * 68, xi, st, pu, &out[b * DD + i]);
        }
        __syncthreads();
    }

    if (tid == 512) out[BB * DD + b] = st.lvsum;
}

extern "C" void kernel_launch(void* const* d_in, const int* in_sizes, int n_in,
                              void* d_out, int out_size) {
    const float* xx   = (const float*)d_in[0];
    const float* muW0 = (const float*)d_in[1];
    const float* mub0 = (const float*)d_in[2];
    const float* muW1 = (const float*)d_in[3];
    const float* mub1 = (const float*)d_in[4];
    const float* muWo = (const float*)d_in[5];
    const float* mubo = (const float*)d_in[6];
    const float* lvW0 = (const float*)d_in[7];
    const float* lvb0 = (const float*)d_in[8];
    const float* lvW1 = (const float*)d_in[9];
    const float* lvb1 = (const float*)d_in[10];
    const float* lvWo = (const float*)d_in[11];
    const float* lvbo = (const float*)d_in[12];
    float* out = (float*)d_out;

    setup_kernel<<<512, 256>>>(muW0, muW1, muWo, mub0, mub1,
                               lvW0, lvW1, lvWo, lvb0, lvb1, mubo, lvbo);
    made_kernel<<<BB, 544>>>(xx, out);
}

// round 6
// speedup vs baseline: 2.9896x; 1.4448x over previous
#include <cuda_runtime.h>
#include <cuda_fp16.h>
#include <math.h>

#define DD 256
#define HH 512
#define BB 128

__device__ __forceinline__ unsigned h2u(__half2 h) {
    return *reinterpret_cast<unsigned*>(&h);
}

// Packed per-(step,thread) wide weights: 8 halves = 16B.
// [w0.mu, w0.lv, w1s0.mu, w1s0.lv, w1s1.mu, w1s1.lv, wo0, wo1]
__device__ uint4 g_wpk[260 * 512];
// 3rd-slot weights for warm-up steps i=2 (idx 0..511) and i=3 (idx 512..1023):
// x = half2(w1s2.mu, w1s2.lv), y = half2(wos2, 0)
__device__ uint2 g_wpk3[2 * 512];
// Combiner urgent records (fp32)
__device__ float g_recS[256 * 40];   // steady 2-slot layout (used i>=4)
__device__ float g_recW[4 * 68];     // warm-up 3-slot layout (i<4)

__device__ __forceinline__ int permf(int p) {
    if (p < 3) return (p == 0) ? 0 : ((p == 1) ? 255 : 510);
    if (p < 6) { int q = p - 3; return (q == 0) ? 1 : ((q == 1) ? 256 : 511); }
    int d = 3 + ((p - 6) >> 1);
    return (((p - 6) & 1) == 0) ? (d - 1) : (d + 254);
}
__device__ __forceinline__ int degf(int p) {
    if (p < 3) return 1;
    if (p < 6) return 2;
    return 3 + ((p - 6) >> 1);
}
__device__ __forceinline__ int Pof(int k) {
    if (k <= 0) return 0;
    if (k == 1) return 3;
    int v = 2 * k + 2;
    return v > HH ? HH : v;
}
__device__ __forceinline__ float elu1(float a) {
    float e = __expf(a) - 1.f;
    return a > 0.f ? a : e;
}

__global__ void setup_kernel(
    const float* __restrict__ W0m, const float* __restrict__ W1m, const float* __restrict__ Wom,
    const float* __restrict__ b0m, const float* __restrict__ b1m,
    const float* __restrict__ W0l, const float* __restrict__ W1l, const float* __restrict__ Wol,
    const float* __restrict__ b0l, const float* __restrict__ b1l,
    const float* __restrict__ bom, const float* __restrict__ bol)
{
    int tid = blockIdx.x * blockDim.x + threadIdx.x;
    int stride = gridDim.x * blockDim.x;

    // packed wide weights
    for (int idx = tid; idx < 256 * 512; idx += stride) {
        int i = idx >> 9, u = idx & 511;
        int du = degf(u), ou = permf(u);
        int onet = u >> 8, ocol = u & 255;
        const float* Wo = onet ? Wol : Wom;

        int w0row = i - 1 < 0 ? 0 : i - 1;
        float m0 = (du >= w0row + 1) ? 1.f : 0.f;
        __half2 hw0 = __floats2half2_rn(m0 * W0m[ou * DD + w0row],
                                        m0 * W0l[ou * DD + w0row]);
        int pB = Pof(i - 2);
        __half2 hw1[2]; float wos[2];
#pragma unroll
        for (int s = 0; s < 2; s++) {
            int p = pB + s; if (p > HH - 1) p = HH - 1;
            int op = permf(p), dp = degf(p);
            float m1 = (du >= dp) ? 1.f : 0.f;
            hw1[s] = __floats2half2_rn(m1 * W1m[ou * HH + op],
                                       m1 * W1l[ou * HH + op]);
            float mo = (ocol >= dp) ? 1.f : 0.f;
            wos[s] = mo * Wo[ocol * HH + op];
        }
        uint4 pk;
        pk.x = h2u(hw0);
        pk.y = h2u(hw1[0]);
        pk.z = h2u(hw1[1]);
        pk.w = h2u(__floats2half2_rn(wos[0], wos[1]));
        g_wpk[i * 512 + u] = pk;
    }
    // 3rd slot for i=2 (row 2) and i=3 (row 5)
    for (int idx = tid; idx < 1024; idx += stride) {
        int j = idx >> 9, u = idx & 511;
        int du = degf(u), ou = permf(u);
        int onet = u >> 8, ocol = u & 255;
        const float* Wo = onet ? Wol : Wom;
        int p = (j == 0) ? 2 : 5;
        int op = permf(p), dp = degf(p);
        float m1 = (du >= dp) ? 1.f : 0.f;
        float mo = (ocol >= dp) ? 1.f : 0.f;
        uint2 pk;
        pk.x = h2u(__floats2half2_rn(m1 * W1m[ou * HH + op],
                                     m1 * W1l[ou * HH + op]));
        pk.y = h2u(__floats2half2_rn(mo * Wo[ocol * HH + op], 0.f));
        g_wpk3[idx] = pk;
    }
    // combiner records
    for (int i = tid; i < 256; i += stride) {
        int cB = Pof(i - 1), cc = Pof(i) - cB;
        int pB = Pof(i - 2), cp = Pof(i - 1) - pB;
        {
            float* r = g_recS + i * 40;
            for (int k = 0; k < 40; k++) r[k] = 0.f;
            int c2 = cc < 2 ? cc : 2, p2 = cp < 2 ? cp : 2;
            for (int s = 0; s < c2; s++) {
                int p = permf(cB + s);
                if (i >= 1) { r[0 + 2 * s] = W0m[p * DD + (i - 1)]; r[1 + 2 * s] = W0l[p * DD + (i - 1)]; }
                r[4 + 2 * s] = b0m[p];  r[5 + 2 * s] = b0l[p];
                r[8 + 2 * s] = b1m[p];  r[9 + 2 * s] = b1l[p];
                r[32 + 2 * s] = Wom[i * HH + p]; r[33 + 2 * s] = Wol[i * HH + p];
            }
            for (int sp = 0; sp < p2; sp++) {
                int pp = permf(pB + sp);
                r[28 + 2 * sp] = Wom[i * HH + pp]; r[29 + 2 * sp] = Wol[i * HH + pp];
                for (int sc = 0; sc < c2; sc++) {
                    int g = permf(cB + sc);
                    r[12 + sp * 4 + 2 * sc] = W1m[g * HH + pp];
                    r[13 + sp * 4 + 2 * sc] = W1l[g * HH + pp];
                }
            }
            for (int sp = 0; sp < c2; sp++)
                for (int sc = 0; sc < c2; sc++) {
                    int pp = permf(cB + sp), g = permf(cB + sc);
                    r[20 + sp * 4 + 2 * sc] = W1m[g * HH + pp];
                    r[21 + sp * 4 + 2 * sc] = W1l[g * HH + pp];
                }
            r[36] = bom[i]; r[37] = bol[i];
        }
        if (i < 4) {
            float* r = g_recW + i * 68;
            for (int k = 0; k < 68; k++) r[k] = 0.f;
            for (int s = 0; s < cc; s++) {
                int p = permf(cB + s);
                if (i >= 1) { r[0 + 2 * s] = W0m[p * DD + (i - 1)]; r[1 + 2 * s] = W0l[p * DD + (i - 1)]; }
                r[6 + 2 * s] = b0m[p];  r[7 + 2 * s] = b0l[p];
                r[12 + 2 * s] = b1m[p]; r[13 + 2 * s] = b1l[p];
                r[60 + 2 * s] = Wom[i * HH + p]; r[61 + 2 * s] = Wol[i * HH + p];
            }
            for (int sp = 0; sp < cp; sp++) {
                int pp = permf(pB + sp);
                r[54 + 2 * sp] = Wom[i * HH + pp]; r[55 + 2 * sp] = Wol[i * HH + pp];
                for (int sc = 0; sc < cc; sc++) {
                    int g = permf(cB + sc);
                    r[18 + sp * 6 + 2 * sc] = W1m[g * HH + pp];
                    r[19 + sp * 6 + 2 * sc] = W1l[g * HH + pp];
                }
            }
            for (int sp = 0; sp < cc; sp++)
                for (int sc = 0; sc < cc; sc++) {
                    int pp = permf(cB + sp), g = permf(cB + sc);
                    r[36 + sp * 6 + 2 * sc] = W1m[g * HH + pp];
                    r[37 + sp * 6 + 2 * sc] = W1l[g * HH + pp];
                }
            r[66] = bom[i]; r[67] = bol[i];
        }
    }
}

// smem layout (floats)
#define OFF_RECS 0
#define OFF_RECW 10240
#define OFF_XS   10512
#define OFF_PUB  10768
#define OFF_PAR  10800
#define SM_FLOATS 10832

struct CombState {
    float h0p[3][2], h1p[3][2];
    float ncol, lvsum;
};

// pr layout: [4s+n]=pa0(slot s,net n), [4s+2+n]=pa1, [8+n]/[10+n]=slot2 pa0/pa1, [12+n]=paout
// pu layout: [0]=ncol, [1..2]=h0s0, [4..5]=h0s1, [8..11]=(h1s0n0,h1s1n0,h1s0n1,h1s1n1),
//            [12..15]=(h0s2n0,h0s2n1,h1s2n0,h1s2n1) (warm only)
__device__ __forceinline__ void comb_steady(const float* __restrict__ pr, const float* __restrict__ r,
                                            float xi, CombState& st, float* __restrict__ pu,
                                            float* __restrict__ outp)
{
    float h0c[2][2], h1c[2][2];
#pragma unroll
    for (int s = 0; s < 2; s++)
#pragma unroll
        for (int n = 0; n < 2; n++)
            h0c[s][n] = elu1(pr[4 * s + n] + st.ncol * r[2 * s + n] + r[4 + 2 * s + n]);
#pragma unroll
    for (int sc = 0; sc < 2; sc++)
#pragma unroll
        for (int n = 0; n < 2; n++) {
            float a = pr[4 * sc + 2 + n] + r[8 + 2 * sc + n];
#pragma unroll
            for (int sp = 0; sp < 2; sp++) a = fmaf(st.h0p[sp][n], r[12 + sp * 4 + 2 * sc + n], a);
#pragma unroll
            for (int sp = 0; sp < 2; sp++) a = fmaf(h0c[sp][n], r[20 + sp * 4 + 2 * sc + n], a);
            h1c[sc][n] = elu1(a);
        }
    float mu = pr[12] + r[36];
    float lv = pr[13] + r[37];
#pragma unroll
    for (int sp = 0; sp < 2; sp++) { mu = fmaf(st.h1p[sp][0], r[28 + 2 * sp], mu); lv = fmaf(st.h1p[sp][1], r[29 + 2 * sp], lv); }
#pragma unroll
    for (int sc = 0; sc < 2; sc++) { mu = fmaf(h1c[sc][0], r[32 + 2 * sc], mu); lv = fmaf(h1c[sc][1], r[33 + 2 * sc], lv); }
    float ls = 0.5f * lv;
    float nc = (xi - mu) * __expf(-ls);
    st.lvsum += ls; st.ncol = nc;
    *outp = nc;
    pu[0] = nc;
    pu[1] = h0c[0][0]; pu[2] = h0c[0][1];
    pu[4] = h0c[1][0]; pu[5] = h0c[1][1];
    pu[8] = h1c[0][0]; pu[9] = h1c[1][0]; pu[10] = h1c[0][1]; pu[11] = h1c[1][1];
#pragma unroll
    for (int s = 0; s < 2; s++)
#pragma unroll
        for (int n = 0; n < 2; n++) { st.h0p[s][n] = h0c[s][n]; st.h1p[s][n] = h1c[s][n]; }
}

__device__ __forceinline__ void comb_warm(const float* __restrict__ pr, const float* __restrict__ r,
                                          float xi, CombState& st, float* __restrict__ pu,
                                          float* __restrict__ outp)
{
    float h0c[3][2], h1c[3][2];
#pragma unroll
    for (int s = 0; s < 3; s++)
#pragma unroll
        for (int n = 0; n < 2; n++) {
            float pa0 = (s < 2) ? pr[4 * s + n] : pr[8 + n];
            h0c[s][n] = elu1(pa0 + st.ncol * r[2 * s + n] + r[6 + 2 * s + n]);
        }
#pragma unroll
    for (int sc = 0; sc < 3; sc++)
#pragma unroll
        for (int n = 0; n < 2; n++) {
            float a = ((sc < 2) ? pr[4 * sc + 2 + n] : pr[10 + n]) + r[12 + 2 * sc + n];
#pragma unroll
            for (int sp = 0; sp < 3; sp++) a = fmaf(st.h0p[sp][n], r[18 + sp * 6 + 2 * sc + n], a);
#pragma unroll
            for (int sp = 0; sp < 3; sp++) a = fmaf(h0c[sp][n], r[36 + sp * 6 + 2 * sc + n], a);
            h1c[sc][n] = elu1(a);
        }
    float mu = pr[12] + r[66];
    float lv = pr[13] + r[67];
#pragma unroll
    for (int sp = 0; sp < 3; sp++) { mu = fmaf(st.h1p[sp][0], r[54 + 2 * sp], mu); lv = fmaf(st.h1p[sp][1], r[55 + 2 * sp], lv); }
#pragma unroll
    for (int sc = 0; sc < 3; sc++) { mu = fmaf(h1c[sc][0], r[60 + 2 * sc], mu); lv = fmaf(h1c[sc][1], r[61 + 2 * sc], lv); }
    float ls = 0.5f * lv;
    float nc = (xi - mu) * __expf(-ls);
    st.lvsum += ls; st.ncol = nc;
    *outp = nc;
    pu[0] = nc;
    pu[1] = h0c[0][0]; pu[2] = h0c[0][1];
    pu[4] = h0c[1][0]; pu[5] = h0c[1][1];
    pu[8] = h1c[0][0]; pu[9] = h1c[1][0]; pu[10] = h1c[0][1]; pu[11] = h1c[1][1];
    pu[12] = h0c[2][0]; pu[13] = h0c[2][1]; pu[14] = h1c[2][0]; pu[15] = h1c[2][1];
#pragma unroll
    for (int s = 0; s < 3; s++)
#pragma unroll
        for (int n = 0; n < 2; n++) { st.h0p[s][n] = h0c[s][n]; st.h1p[s][n] = h1c[s][n]; }
}

// 128 CTAs (one batch element each), 544 threads:
// tid<512: wide owner of unit tid (both nets) + output column (tid>>8, tid&255)
// tid==512: combiner (serial critical path)
__global__ __launch_bounds__(544, 1) void made_kernel(
    const float* __restrict__ x, float* __restrict__ out)
{
    __shared__ __align__(16) float SM[SM_FLOATS];

    const int tid = threadIdx.x;
    const int b = blockIdx.x;

    {
        const float4* src = (const float4*)g_recS;
        float4* dst = (float4*)(SM + OFF_RECS);
        for (int k = tid; k < (256 * 40) / 4; k += 544) dst[k] = src[k];
        for (int k = tid; k < 4 * 68; k += 544) SM[OFF_RECW + k] = g_recW[k];
        if (tid < 256) SM[OFF_XS + tid] = x[b * DD + tid];
        for (int k = tid; k < 64; k += 544) SM[OFF_PUB + k] = 0.f;
    }

    const int u = tid < 512 ? tid : 0;
    const int du = degf(u);
    const int su = u - Pof(du - 1);
    const int onet = (tid >> 8) & 1;
    const int ocol = tid & 255;

    float a0n0 = 0.f, a0n1 = 0.f, a1n0 = 0.f, a1n1 = 0.f, aout = 0.f;

    uint4 Wc, Wn, Wm;
    const uint4* wp = g_wpk + u;
    Wc = wp[0]; Wn = wp[512]; Wm = wp[1024];
    wp += 1536;
    const uint2 w3a = g_wpk3[u];
    const uint2 w3b = g_wpk3[512 + u];

    CombState st;
#pragma unroll
    for (int s = 0; s < 3; s++)
#pragma unroll
        for (int n = 0; n < 2; n++) { st.h0p[s][n] = 0.f; st.h1p[s][n] = 0.f; }
    st.ncol = 0.f; st.lvsum = 0.f;

    __syncthreads();

#pragma unroll 1
    for (int i = 0; i < DD; i++) {
        if (tid < 512) {
            const float* pb = SM + OFF_PUB + (((i + 1) & 1) << 4);
            const float4 p0 = *(const float4*)pb;              // ncol, h0s0n0, h0s0n1, -
            const float2 p1 = *(const float2*)(pb + 4);        // h0s1n0, h0s1n1
            const float2 ph = *(const float2*)(pb + 8 + 2 * onet);
            const float2 w0 = __half22float2(*(const __half2*)&Wc.x);
            const float2 wA = __half22float2(*(const __half2*)&Wc.y);
            const float2 wB = __half22float2(*(const __half2*)&Wc.z);
            const float2 wo = __half22float2(*(const __half2*)&Wc.w);
            a0n0 = fmaf(p0.x, w0.x, a0n0); a0n1 = fmaf(p0.x, w0.y, a0n1);
            a1n0 = fmaf(p0.y, wA.x, a1n0); a1n1 = fmaf(p0.z, wA.y, a1n1);
            a1n0 = fmaf(p1.x, wB.x, a1n0); a1n1 = fmaf(p1.y, wB.y, a1n1);
            aout = fmaf(ph.x, wo.x, aout); aout = fmaf(ph.y, wo.y, aout);
            if ((unsigned)(i - 2) < 2u) {  // warm-up slot-2 multiplies (i = 2, 3)
                const float4 pe = *(const float4*)(pb + 12);
                uint2 w3 = (i == 2) ? w3a : w3b;
                const float2 w12 = __half22float2(*(const __half2*)&w3.x);
                const float2 wo2 = __half22float2(*(const __half2*)&w3.y);
                a1n0 = fmaf(pe.x, w12.x, a1n0); a1n1 = fmaf(pe.y, w12.y, a1n1);
                aout = fmaf(onet ? pe.w : pe.z, wo2.x, aout);
            }
            float* pw = SM + OFF_PAR + (((i + 1) & 1) << 4);
            if (du == i + 1) {
                const int off = (su < 2) ? (su << 2) : 8;
                pw[off] = a0n0; pw[off + 1] = a0n1;
                pw[off + 2] = a1n0; pw[off + 3] = a1n1;
            }
            if (ocol == i + 1) pw[12 + onet] = aout;
            // rotate + prefetch (2 steps ahead)
            Wc = Wn; Wn = Wm; Wm = *wp; wp += 512;
        } else if (tid == 512) {
            const float* pr = SM + OFF_PAR + ((i & 1) << 4);
            float* pu = SM + OFF_PUB + ((i & 1) << 4);
            const float xi = SM[OFF_XS + i];
            if (i >= 4)
                comb_steady(pr, SM + OFF_RECS + i * 40, xi, st, pu, &out[b * DD + i]);
            else
                comb_warm(pr, SM + OFF_RECW + i * 68, xi, st, pu, &out[b * DD + i]);
        }
        __syncthreads();
    }

    if (tid == 512) out[BB * DD + b] = st.lvsum;
}

extern "C" void kernel_launch(void* const* d_in, const int* in_sizes, int n_in,
                              void* d_out, int out_size) {
    const float* xx   = (const float*)d_in[0];
    const float* muW0 = (const float*)d_in[1];
    const float* mub0 = (const float*)d_in[2];
    const float* muW1 = (const float*)d_in[3];
    const float* mub1 = (const float*)d_in[4];
    const float* muWo = (const float*)d_in[5];
    const float* mubo = (const float*)d_in[6];
    const float* lvW0 = (const float*)d_in[7];
    const float* lvb0 = (const float*)d_in[8];
    const float* lvW1 = (const float*)d_in[9];
    const float* lvb1 = (const float*)d_in[10];
    const float* lvWo = (const float*)d_in[11];
    const float* lvbo = (const float*)d_in[12];
    float* out = (float*)d_out;

    setup_kernel<<<512, 256>>>(muW0, muW1, muWo, mub0, mub1,
                               lvW0, lvW1, lvWo, lvb0, lvb1, mubo, lvbo);
    made_kernel<<<BB, 544>>>(xx, out);
}

// round 7
// speedup vs baseline: 3.1041x; 1.0383x over previous
#include <cuda_runtime.h>
#include <math.h>

#define DD 256
#define HH 512
#define BB 128

__device__ __forceinline__ unsigned long long packf2(float lo, float hi) {
    return ((unsigned long long)__float_as_uint(hi) << 32) | (unsigned long long)__float_as_uint(lo);
}
__device__ __forceinline__ float lof(unsigned long long v) { return __uint_as_float((unsigned)v); }
__device__ __forceinline__ float hif(unsigned long long v) { return __uint_as_float((unsigned)(v >> 32)); }
__device__ __forceinline__ void ffma2(unsigned long long& d, unsigned long long a, unsigned long long b) {
    asm("fma.rn.f32x2 %0, %1, %2, %0;" : "+l"(d) : "l"(a), "l"(b));
}

// Per-(step,u) wide weights, fp32 pairs. A = [ (w0.mu,w0.lv), (w1s0.mu,w1s0.lv) ],
// B = [ (w1s1.mu,w1s1.lv), (wo0,wo1) ].  260 rows so 2-ahead prefetch stays in bounds.
__device__ ulonglong2 g_wpkA[260 * 512];
__device__ ulonglong2 g_wpkB[260 * 512];
// Warm-up 3rd-slot weights: idx<512 -> i=2, idx>=512 -> i=3
__device__ unsigned long long g_w3p[2 * 512];  // (w1s2.mu, w1s2.lv)
__device__ float g_w3o[2 * 512];               // wos2
// Combiner urgent records (fp32)
__device__ float g_recS[256 * 40];   // steady 2-slot layout (used i>=4)
__device__ float g_recW[4 * 68];     // warm-up 3-slot layout (i<4)

__device__ __forceinline__ int permf(int p) {
    if (p < 3) return (p == 0) ? 0 : ((p == 1) ? 255 : 510);
    if (p < 6) { int q = p - 3; return (q == 0) ? 1 : ((q == 1) ? 256 : 511); }
    int d = 3 + ((p - 6) >> 1);
    return (((p - 6) & 1) == 0) ? (d - 1) : (d + 254);
}
__device__ __forceinline__ int degf(int p) {
    if (p < 3) return 1;
    if (p < 6) return 2;
    return 3 + ((p - 6) >> 1);
}
__device__ __forceinline__ int Pof(int k) {
    if (k <= 0) return 0;
    if (k == 1) return 3;
    int v = 2 * k + 2;
    return v > HH ? HH : v;
}
__device__ __forceinline__ float elu1(float a) {
    float e = __expf(a) - 1.f;
    return a > 0.f ? a : e;
}

__global__ void setup_kernel(
    const float* __restrict__ W0m, const float* __restrict__ W1m, const float* __restrict__ Wom,
    const float* __restrict__ b0m, const float* __restrict__ b1m,
    const float* __restrict__ W0l, const float* __restrict__ W1l, const float* __restrict__ Wol,
    const float* __restrict__ b0l, const float* __restrict__ b1l,
    const float* __restrict__ bom, const float* __restrict__ bol)
{
    int tid = blockIdx.x * blockDim.x + threadIdx.x;
    int stride = gridDim.x * blockDim.x;

    // packed wide weights (fp32)
    for (int idx = tid; idx < 256 * 512; idx += stride) {
        int i = idx >> 9, u = idx & 511;
        int du = degf(u), ou = permf(u);
        int onet = u >> 8, ocol = u & 255;
        const float* Wo = onet ? Wol : Wom;

        int w0row = i - 1 < 0 ? 0 : i - 1;
        float m0 = (du >= w0row + 1) ? 1.f : 0.f;
        float w0mu = m0 * W0m[ou * DD + w0row];
        float w0lv = m0 * W0l[ou * DD + w0row];

        int pB = Pof(i - 2);
        float w1s[2][2], wos[2];
#pragma unroll
        for (int s = 0; s < 2; s++) {
            int p = pB + s; if (p > HH - 1) p = HH - 1;
            int op = permf(p), dp = degf(p);
            float m1 = (du >= dp) ? 1.f : 0.f;
            w1s[s][0] = m1 * W1m[ou * HH + op];
            w1s[s][1] = m1 * W1l[ou * HH + op];
            float mo = (ocol >= dp) ? 1.f : 0.f;
            wos[s] = mo * Wo[ocol * HH + op];
        }
        g_wpkA[i * 512 + u] = make_ulonglong2(packf2(w0mu, w0lv), packf2(w1s[0][0], w1s[0][1]));
        g_wpkB[i * 512 + u] = make_ulonglong2(packf2(w1s[1][0], w1s[1][1]), packf2(wos[0], wos[1]));
    }
    // 3rd slot for i=2 (p=2) and i=3 (p=5)
    for (int idx = tid; idx < 1024; idx += stride) {
        int j = idx >> 9, u = idx & 511;
        int du = degf(u), ou = permf(u);
        int onet = u >> 8, ocol = u & 255;
        const float* Wo = onet ? Wol : Wom;
        int p = (j == 0) ? 2 : 5;
        int op = permf(p), dp = degf(p);
        float m1 = (du >= dp) ? 1.f : 0.f;
        float mo = (ocol >= dp) ? 1.f : 0.f;
        g_w3p[idx] = packf2(m1 * W1m[ou * HH + op], m1 * W1l[ou * HH + op]);
        g_w3o[idx] = mo * Wo[ocol * HH + op];
    }
    // combiner records
    for (int i = tid; i < 256; i += stride) {
        int cB = Pof(i - 1), cc = Pof(i) - cB;
        int pB = Pof(i - 2), cp = Pof(i - 1) - pB;
        {
            float* r = g_recS + i * 40;
            for (int k = 0; k < 40; k++) r[k] = 0.f;
            int c2 = cc < 2 ? cc : 2, p2 = cp < 2 ? cp : 2;
            for (int s = 0; s < c2; s++) {
                int p = permf(cB + s);
                if (i >= 1) { r[0 + 2 * s] = W0m[p * DD + (i - 1)]; r[1 + 2 * s] = W0l[p * DD + (i - 1)]; }
                r[4 + 2 * s] = b0m[p];  r[5 + 2 * s] = b0l[p];
                r[8 + 2 * s] = b1m[p];  r[9 + 2 * s] = b1l[p];
                r[32 + 2 * s] = Wom[i * HH + p]; r[33 + 2 * s] = Wol[i * HH + p];
            }
            for (int sp = 0; sp < p2; sp++) {
                int pp = permf(pB + sp);
                r[28 + 2 * sp] = Wom[i * HH + pp]; r[29 + 2 * sp] = Wol[i * HH + pp];
                for (int sc = 0; sc < c2; sc++) {
                    int g = permf(cB + sc);
                    r[12 + sp * 4 + 2 * sc] = W1m[g * HH + pp];
                    r[13 + sp * 4 + 2 * sc] = W1l[g * HH + pp];
                }
            }
            for (int sp = 0; sp < c2; sp++)
                for (int sc = 0; sc < c2; sc++) {
                    int pp = permf(cB + sp), g = permf(cB + sc);
                    r[20 + sp * 4 + 2 * sc] = W1m[g * HH + pp];
                    r[21 + sp * 4 + 2 * sc] = W1l[g * HH + pp];
                }
            r[36] = bom[i]; r[37] = bol[i];
        }
        if (i < 4) {
            float* r = g_recW + i * 68;
            for (int k = 0; k < 68; k++) r[k] = 0.f;
            for (int s = 0; s < cc; s++) {
                int p = permf(cB + s);
                if (i >= 1) { r[0 + 2 * s] = W0m[p * DD + (i - 1)]; r[1 + 2 * s] = W0l[p * DD + (i - 1)]; }
                r[6 + 2 * s] = b0m[p];  r[7 + 2 * s] = b0l[p];
                r[12 + 2 * s] = b1m[p]; r[13 + 2 * s] = b1l[p];
                r[60 + 2 * s] = Wom[i * HH + p]; r[61 + 2 * s] = Wol[i * HH + p];
            }
            for (int sp = 0; sp < cp; sp++) {
                int pp = permf(pB + sp);
                r[54 + 2 * sp] = Wom[i * HH + pp]; r[55 + 2 * sp] = Wol[i * HH + pp];
                for (int sc = 0; sc < cc; sc++) {
                    int g = permf(cB + sc);
                    r[18 + sp * 6 + 2 * sc] = W1m[g * HH + pp];
                    r[19 + sp * 6 + 2 * sc] = W1l[g * HH + pp];
                }
            }
            for (int sp = 0; sp < cc; sp++)
                for (int sc = 0; sc < cc; sc++) {
                    int pp = permf(cB + sp), g = permf(cB + sc);
                    r[36 + sp * 6 + 2 * sc] = W1m[g * HH + pp];
                    r[37 + sp * 6 + 2 * sc] = W1l[g * HH + pp];
                }
            r[66] = bom[i]; r[67] = bol[i];
        }
    }
}

// smem layout (floats)
#define OFF_RECS 0
#define OFF_RECW 10240
#define OFF_XS   10512
#define OFF_PUB  10768
#define OFF_PAR  10800
#define SM_FLOATS 10832

struct CombState {
    float h0p[3][2], h1p[3][2];
    float ncol, lvsum;
};

// pr layout (unchanged): [4s+n]=pa0 slot s net n, [4s+2+n]=pa1; slot2 pa0 [8..9], pa1 [10..11];
//                        paout [12+n]
// pu layout (pairs, 8B aligned): [0..1]=(ncol,ncol), [2..3]=h0s0(n0,n1), [4..5]=h0s1(n0,n1),
//   [6..7]=(h1s0n0,h1s1n0), [8..9]=(h1s0n1,h1s1n1); warm: [10..11]=h0s2(n0,n1), [12..13]=(h1s2n0,h1s2n1)
__device__ __forceinline__ void comb_steady(const float* __restrict__ pr, const float* __restrict__ r,
                                            float xi, CombState& st, float* __restrict__ pu,
                                            float* __restrict__ outp)
{
    float h0c[2][2], h1c[2][2];
#pragma unroll
    for (int s = 0; s < 2; s++)
#pragma unroll
        for (int n = 0; n < 2; n++)
            h0c[s][n] = elu1(pr[4 * s + n] + st.ncol * r[2 * s + n] + r[4 + 2 * s + n]);
#pragma unroll
    for (int sc = 0; sc < 2; sc++)
#pragma unroll
        for (int n = 0; n < 2; n++) {
            float a = pr[4 * sc + 2 + n] + r[8 + 2 * sc + n];
#pragma unroll
            for (int sp = 0; sp < 2; sp++) a = fmaf(st.h0p[sp][n], r[12 + sp * 4 + 2 * sc + n], a);
#pragma unroll
            for (int sp = 0; sp < 2; sp++) a = fmaf(h0c[sp][n], r[20 + sp * 4 + 2 * sc + n], a);
            h1c[sc][n] = elu1(a);
        }
    float mu = pr[12] + r[36];
    float lv = pr[13] + r[37];
#pragma unroll
    for (int sp = 0; sp < 2; sp++) { mu = fmaf(st.h1p[sp][0], r[28 + 2 * sp], mu); lv = fmaf(st.h1p[sp][1], r[29 + 2 * sp], lv); }
#pragma unroll
    for (int sc = 0; sc < 2; sc++) { mu = fmaf(h1c[sc][0], r[32 + 2 * sc], mu); lv = fmaf(h1c[sc][1], r[33 + 2 * sc], lv); }
    float ls = 0.5f * lv;
    float nc = (xi - mu) * __expf(-ls);
    st.lvsum += ls; st.ncol = nc;
    *outp = nc;
    *(unsigned long long*)(pu + 0) = packf2(nc, nc);
    *(unsigned long long*)(pu + 2) = packf2(h0c[0][0], h0c[0][1]);
    *(unsigned long long*)(pu + 4) = packf2(h0c[1][0], h0c[1][1]);
    *(unsigned long long*)(pu + 6) = packf2(h1c[0][0], h1c[1][0]);
    *(unsigned long long*)(pu + 8) = packf2(h1c[0][1], h1c[1][1]);
#pragma unroll
    for (int s = 0; s < 2; s++)
#pragma unroll
        for (int n = 0; n < 2; n++) { st.h0p[s][n] = h0c[s][n]; st.h1p[s][n] = h1c[s][n]; }
}

__device__ __forceinline__ void comb_warm(const float* __restrict__ pr, const float* __restrict__ r,
                                          float xi, CombState& st, float* __restrict__ pu,
                                          float* __restrict__ outp)
{
    float h0c[3][2], h1c[3][2];
#pragma unroll
    for (int s = 0; s < 3; s++)
#pragma unroll
        for (int n = 0; n < 2; n++) {
            float pa0 = (s < 2) ? pr[4 * s + n] : pr[8 + n];
            h0c[s][n] = elu1(pa0 + st.ncol * r[2 * s + n] + r[6 + 2 * s + n]);
        }
#pragma unroll
    for (int sc = 0; sc < 3; sc++)
#pragma unroll
        for (int n = 0; n < 2; n++) {
            float a = ((sc < 2) ? pr[4 * sc + 2 + n] : pr[10 + n]) + r[12 + 2 * sc + n];
#pragma unroll
            for (int sp = 0; sp < 3; sp++) a = fmaf(st.h0p[sp][n], r[18 + sp * 6 + 2 * sc + n], a);
#pragma unroll
            for (int sp = 0; sp < 3; sp++) a = fmaf(h0c[sp][n], r[36 + sp * 6 + 2 * sc + n], a);
            h1c[sc][n] = elu1(a);
        }
    float mu = pr[12] + r[66];
    float lv = pr[13] + r[67];
#pragma unroll
    for (int sp = 0; sp < 3; sp++) { mu = fmaf(st.h1p[sp][0], r[54 + 2 * sp], mu); lv = fmaf(st.h1p[sp][1], r[55 + 2 * sp], lv); }
#pragma unroll
    for (int sc = 0; sc < 3; sc++) { mu = fmaf(h1c[sc][0], r[60 + 2 * sc], mu); lv = fmaf(h1c[sc][1], r[61 + 2 * sc], lv); }
    float ls = 0.5f * lv;
    float nc = (xi - mu) * __expf(-ls);
    st.lvsum += ls; st.ncol = nc;
    *outp = nc;
    *(unsigned long long*)(pu + 0) = packf2(nc, nc);
    *(unsigned long long*)(pu + 2) = packf2(h0c[0][0], h0c[0][1]);
    *(unsigned long long*)(pu + 4) = packf2(h0c[1][0], h0c[1][1]);
    *(unsigned long long*)(pu + 6) = packf2(h1c[0][0], h1c[1][0]);
    *(unsigned long long*)(pu + 8) = packf2(h1c[0][1], h1c[1][1]);
    *(unsigned long long*)(pu + 10) = packf2(h0c[2][0], h0c[2][1]);
    *(unsigned long long*)(pu + 12) = packf2(h1c[2][0], h1c[2][1]);
#pragma unroll
    for (int s = 0; s < 3; s++)
#pragma unroll
        for (int n = 0; n < 2; n++) { st.h0p[s][n] = h0c[s][n]; st.h1p[s][n] = h1c[s][n]; }
}

__device__ __forceinline__ void wide_step(
    int i, const float* __restrict__ pb, const float* __restrict__ pbh,
    const float* __restrict__ pb12,
    ulonglong2 Wa, ulonglong2 Wb,
    unsigned long long& A0, unsigned long long& A1, unsigned long long& AO, float& aoutC,
    int pubA, int pubO, float* __restrict__ pwA, float* __restrict__ pwO,
    unsigned long long w3p2, unsigned long long w3p3, float w3o2, float w3o3)
{
    const unsigned long long nc2  = *(const unsigned long long*)(pb + 0);
    const unsigned long long h0s0 = *(const unsigned long long*)(pb + 2);
    const unsigned long long h0s1 = *(const unsigned long long*)(pb + 4);
    const unsigned long long h1p  = *(const unsigned long long*)pbh;
    ffma2(A0, nc2, Wa.x);
    ffma2(A1, h0s0, Wa.y);
    ffma2(A1, h0s1, Wb.x);
    ffma2(AO, h1p, Wb.y);
    if ((unsigned)(i - 2) < 2u) {  // warm-up 3rd slot (i = 2, 3)
        const unsigned long long h0s2 = *(const unsigned long long*)(pb + 10);
        ffma2(A1, h0s2, (i == 2) ? w3p2 : w3p3);
        aoutC = fmaf(*pb12, (i == 2) ? w3o2 : w3o3, aoutC);
    }
    if (i == pubA) {
        *(unsigned long long*)(pwA + 0) = A0;
        *(unsigned long long*)(pwA + 2) = A1;
    }
    if (i == pubO) *pwO = lof(AO) + hif(AO) + aoutC;
}

// 128 CTAs (one batch element each), 544 threads:
// tid<512: wide owner of unit tid (both nets) + output column (tid>>8, tid&255)
// tid==512: combiner (serial critical path)
__global__ __launch_bounds__(544, 1) void made_kernel(
    const float* __restrict__ x, float* __restrict__ out)
{
    __shared__ __align__(16) float SM[SM_FLOATS];

    const int tid = threadIdx.x;
    const int b = blockIdx.x;

    {
        const float4* src = (const float4*)g_recS;
        float4* dst = (float4*)(SM + OFF_RECS);
        for (int k = tid; k < (256 * 40) / 4; k += 544) dst[k] = src[k];
        for (int k = tid; k < 4 * 68; k += 544) SM[OFF_RECW + k] = g_recW[k];
        if (tid < 256) SM[OFF_XS + tid] = x[b * DD + tid];
        for (int k = tid; k < 64; k += 544) SM[OFF_PUB + k] = 0.f;
    }

    const int u = tid < 512 ? tid : 0;
    const int du = degf(u);
    const int su = u - Pof(du - 1);
    const int onet = (tid >> 8) & 1;
    const int ocol = tid & 255;
    const int pubA = du - 1;           // publish accumulators at step i == pubA
    const int pubO = ocol - 1;         // publish aout at step i == pubO (ocol 0 never)
    const int off = (su < 2) ? (su << 2) : 8;

    float* const pub0 = SM + OFF_PUB;
    float* const pub1 = SM + OFF_PUB + 16;
    float* const par0 = SM + OFF_PAR;
    float* const par1 = SM + OFF_PAR + 16;
    float* const pwA0 = par0 + off;
    float* const pwA1 = par1 + off;
    float* const pwO0 = par0 + 12 + onet;
    float* const pwO1 = par1 + 12 + onet;
    const float* const pbh0 = pub0 + 6 + 2 * onet;
    const float* const pbh1 = pub1 + 6 + 2 * onet;
    const float* const pb120 = pub0 + 12 + onet;
    const float* const pb121 = pub1 + 12 + onet;

    unsigned long long A0 = 0, A1 = 0, AO = 0;
    float aoutC = 0.f;

    const ulonglong2* wpA = g_wpkA + u;
    const ulonglong2* wpB = g_wpkB + u;
    ulonglong2 Wa0 = wpA[0],   Wb0 = wpB[0];
    ulonglong2 Wa1 = wpA[512], Wb1 = wpB[512];
    wpA += 1024; wpB += 1024;
    const unsigned long long w3p2 = g_w3p[u], w3p3 = g_w3p[512 + u];
    const float w3o2 = g_w3o[u], w3o3 = g_w3o[512 + u];

    CombState st;
#pragma unroll
    for (int s = 0; s < 3; s++)
#pragma unroll
        for (int n = 0; n < 2; n++) { st.h0p[s][n] = 0.f; st.h1p[s][n] = 0.f; }
    st.ncol = 0.f; st.lvsum = 0.f;

    float* const outb = out + b * DD;

    __syncthreads();

#pragma unroll 1
    for (int i = 0; i < DD; i += 2) {
        // even sub-step: wide reads pub1/writes par1; combiner reads par0/writes pub0
        if (tid < 512) {
            wide_step(i, pub1, pbh1, pb121, Wa0, Wb0, A0, A1, AO, aoutC,
                      pubA, pubO, pwA1, pwO1, w3p2, w3p3, w3o2, w3o3);
            Wa0 = wpA[0]; Wb0 = wpB[0];
        } else if (tid == 512) {
            const float xi = SM[OFF_XS + i];
            if (i >= 4) comb_steady(par0, SM + OFF_RECS + i * 40, xi, st, pub0, outb + i);
            else        comb_warm(par0, SM + OFF_RECW + i * 68, xi, st, pub0, outb + i);
        }
        __syncthreads();
        // odd sub-step: wide reads pub0/writes par0; combiner reads par1/writes pub1
        if (tid < 512) {
            wide_step(i + 1, pub0, pbh0, pb120, Wa1, Wb1, A0, A1, AO, aoutC,
                      pubA, pubO, pwA0, pwO0, w3p2, w3p3, w3o2, w3o3);
            Wa1 = wpA[512]; Wb1 = wpB[512];
            wpA += 1024; wpB += 1024;
        } else if (tid == 512) {
            const float xi = SM[OFF_XS + i + 1];
            if (i + 1 >= 4) comb_steady(par1, SM + OFF_RECS + (i + 1) * 40, xi, st, pub1, outb + i + 1);
            else            comb_warm(par1, SM + OFF_RECW + (i + 1) * 68, xi, st, pub1, outb + i + 1);
        }
        __syncthreads();
    }

    if (tid == 512) out[BB * DD + b] = st.lvsum;
}

extern "C" void kernel_launch(void* const* d_in, const int* in_sizes, int n_in,
                              void* d_out, int out_size) {
    const float* xx   = (const float*)d_in[0];
    const float* muW0 = (const float*)d_in[1];
    const float* mub0 = (const float*)d_in[2];
    const float* muW1 = (const float*)d_in[3];
    const float* mub1 = (const float*)d_in[4];
    const float* muWo = (const float*)d_in[5];
    const float* mubo = (const float*)d_in[6];
    const float* lvW0 = (const float*)d_in[7];
    const float* lvb0 = (const float*)d_in[8];
    const float* lvW1 = (const float*)d_in[9];
    const float* lvb1 = (const float*)d_in[10];
    const float* lvWo = (const float*)d_in[11];
    const float* lvbo = (const float*)d_in[12];
    float* out = (float*)d_out;

    setup_kernel<<<512, 256>>>(muW0, muW1, muWo, mub0, mub1,
                               lvW0, lvW1, lvWo, lvb0, lvb1, mubo, lvbo);
    made_kernel<<<BB, 544>>>(xx, out);
}